// round 7
// baseline (speedup 1.0000x reference)
#include <cuda_runtime.h>
#include <cstddef>

#define NPIX      49152
#define NBATCH    16
#define NBUCKETS  8
#define C_IN      16
#define OUT_DIM   64
#define PROJ_IN   136      // 8*16 + 8
#define PROJ_MID  128
#define ROWS      (NBATCH * NPIX)          // 786432
#define LN_EPS    1e-5f

#define TILE_M    64
#define MLP_THREADS 256
#define W1TS      138      // W1^T row stride (floats) -> conflict-free banks
#define W2TS      130      // W2^T row stride
#define HS        130      // H tile stride

// Scratch: per-cell channel sums + counts. Zero-initialized at module load;
// k_mlp re-zeros the region it consumes so every replay sees a clean buffer.
__device__ float g_sums[(size_t)ROWS * NBUCKETS * C_IN];   // ~402 MB
__device__ float g_counts[(size_t)ROWS * NBUCKETS];        // ~25 MB

__device__ __forceinline__ void ffma2(unsigned long long& d,
                                      unsigned long long a,
                                      unsigned long long b) {
    asm("fma.rn.f32x2 %0, %1, %2, %3;" : "=l"(d) : "l"(a), "l"(b), "l"(d));
}
__device__ __forceinline__ float pairsum(unsigned long long v) {
    float lo, hi;
    asm("mov.b64 {%0, %1}, %2;" : "=f"(lo), "=f"(hi) : "l"(v));
    return lo + hi;
}
__device__ __forceinline__ unsigned long long lds64(const float* p) {
    return *(const unsigned long long*)p;
}

// ---------------------------------------------------------------------------
// Phase 1: scatter-add. Grid-stride; vector red.v4 for 16 channels + count.
// ---------------------------------------------------------------------------
__global__ void __launch_bounds__(256) k_scatter(
    const float4* __restrict__ x4,
    const int*    __restrict__ bidx,
    const int*    __restrict__ pix,
    const int*    __restrict__ bkt,
    int n)
{
    for (int i = blockIdx.x * 256 + threadIdx.x; i < n; i += gridDim.x * 256) {
        size_t flat = ((size_t)bidx[i] * NPIX + (size_t)pix[i]) * NBUCKETS + (size_t)bkt[i];
        float* dst = g_sums + flat * C_IN;

        float4 v0 = x4[(size_t)i * 4 + 0];
        float4 v1 = x4[(size_t)i * 4 + 1];
        float4 v2 = x4[(size_t)i * 4 + 2];
        float4 v3 = x4[(size_t)i * 4 + 3];

        asm volatile("red.global.add.v4.f32 [%0], {%1,%2,%3,%4};"
                     :: "l"(dst +  0), "f"(v0.x), "f"(v0.y), "f"(v0.z), "f"(v0.w) : "memory");
        asm volatile("red.global.add.v4.f32 [%0], {%1,%2,%3,%4};"
                     :: "l"(dst +  4), "f"(v1.x), "f"(v1.y), "f"(v1.z), "f"(v1.w) : "memory");
        asm volatile("red.global.add.v4.f32 [%0], {%1,%2,%3,%4};"
                     :: "l"(dst +  8), "f"(v2.x), "f"(v2.y), "f"(v2.z), "f"(v2.w) : "memory");
        asm volatile("red.global.add.v4.f32 [%0], {%1,%2,%3,%4};"
                     :: "l"(dst + 12), "f"(v3.x), "f"(v3.y), "f"(v3.z), "f"(v3.w) : "memory");

        atomicAdd(g_counts + flat, 1.0f);
    }
}

// ---------------------------------------------------------------------------
// Phase 2: mean -> concat(present) -> GEMM1 -> LN -> SiLU -> GEMM2, fused.
// 64 rows/block, 256 threads, 2 CTAs/SM.  k-parity f32x2: acc.lo/.hi hold
// even/odd-k partial sums; W tiles stored TRANSPOSED so both FFMA2 operands
// load naturally (no duplication MOVs).  Column map col = tx + 16*j keeps
// all transposed-weight LDS.64 conflict-free (strides 138 / 130).
//
// smem (floats):
//   [0)      region0: W1T 128x138 = 17664   (after GEMM1 reused as:
//              W2T 64x130 = 8320 | sRed@8320: 64x16 float2 | sStat@10368)
//   [17664)  sA 64x136 = 8704               (after GEMM1 reused as H 64x130)
//   [26368)  sCnt 512 | sB1 128 | sG 128 | sBt 128 | sB2 64
// total 27328 floats = 109312 B -> 2 CTAs/SM
// ---------------------------------------------------------------------------
#define SMEM_FLOATS 27328
#define SMEM_BYTES  (SMEM_FLOATS * 4)

__global__ void __launch_bounds__(MLP_THREADS, 2) k_mlp(
    const float* __restrict__ W1, const float* __restrict__ b1,
    const float* __restrict__ gamma, const float* __restrict__ beta,
    const float* __restrict__ W2, const float* __restrict__ b2,
    float* __restrict__ out)
{
    extern __shared__ float sm[];
    float*  sW1T = sm;                       // 17664
    float*  sW2T = sm;                       // reuse after GEMM1 (8320)
    float2* sRed = (float2*)(sm + 8320);     // 64*16 float2
    float2* sStat = (float2*)(sm + 10368);   // 64 float2
    float*  sA   = sm + 17664;               // 8704, reused as H (stride HS)
    float*  sH   = sA;
    float*  sCnt = sm + 26368;
    float*  sB1  = sCnt + 512;
    float*  sG   = sB1 + 128;
    float*  sBt  = sG + 128;
    float*  sB2  = sBt + 128;

    const int t  = threadIdx.x;
    const int tx = t & 15;        // 16 column groups
    const int ty = t >> 4;        // 16 row groups of 4
    const int r0 = ty * 4;
    const int rowStart = blockIdx.x * TILE_M;

    // ---- stage W1 transposed + biases + counts/presence ----
    for (int i = t; i < PROJ_IN * PROJ_MID; i += MLP_THREADS) {
        int k = i >> 7, col = i & 127;
        sW1T[col * W1TS + k] = W1[i];
    }
    if (t < 128) { sB1[t] = b1[t]; sG[t] = gamma[t]; sBt[t] = beta[t]; }
    else if (t < 192) sB2[t - 128] = b2[t - 128];
    {
        float* gc = g_counts + (size_t)rowStart * NBUCKETS;
        for (int i = t; i < TILE_M * NBUCKETS; i += MLP_THREADS) {
            float c = gc[i];
            gc[i] = 0.0f;
            sCnt[i] = c;
            int row = i >> 3, kb = i & 7;
            sA[row * PROJ_IN + PROJ_MID + kb] = (c > 0.0f) ? 1.0f : 0.0f;
        }
    }
    __syncthreads();

    // ---- sums -> means into sA; zero g_sums region ----
    {
        float4* gs = (float4*)(g_sums + (size_t)rowStart * (NBUCKETS * C_IN));
        for (int q = t; q < TILE_M * 32; q += MLP_THREADS) {
            float4 v = gs[q];
            gs[q] = make_float4(0.f, 0.f, 0.f, 0.f);
            int row = q >> 5, f = q & 31, kb = f >> 2;
            float inv = 1.0f / fmaxf(sCnt[row * 8 + kb], 1.0f);
            v.x *= inv; v.y *= inv; v.z *= inv; v.w *= inv;
            *(float4*)&sA[row * PROJ_IN + f * 4] = v;
        }
    }
    __syncthreads();

    // ---- GEMM1: k-parity f32x2, 4 rows x 8 cols per thread ----
    unsigned long long acc1[4][8];
    #pragma unroll
    for (int i = 0; i < 4; i++)
        #pragma unroll
        for (int j = 0; j < 8; j++) acc1[i][j] = 0ull;

    {
        const float* pA = sA + r0 * PROJ_IN;
        const float* pW = sW1T + tx * W1TS;
        #pragma unroll 2
        for (int p = 0; p < PROJ_IN / 2; ++p) {
            unsigned long long a[4], w[8];
            #pragma unroll
            for (int i = 0; i < 4; i++) a[i] = lds64(pA + i * PROJ_IN + 2 * p);
            #pragma unroll
            for (int j = 0; j < 8; j++) w[j] = lds64(pW + j * 16 * W1TS + 2 * p);
            #pragma unroll
            for (int i = 0; i < 4; i++)
                #pragma unroll
                for (int j = 0; j < 8; j++) ffma2(acc1[i][j], a[i], w[j]);
        }
    }
    __syncthreads();   // all W1T + sA reads done; region0 tail & sA reusable

    // ---- stage W2 transposed (into retired W1T space) ----
    for (int i = t; i < PROJ_MID * OUT_DIM; i += MLP_THREADS) {
        int k = i >> 6, col = i & 63;
        sW2T[col * W2TS + k] = W2[i];
    }

    // ---- h = acc + b1 ; per-row partial stats ----
    float h[4][8];
    #pragma unroll
    for (int i = 0; i < 4; i++) {
        float s = 0.f, s2 = 0.f;
        #pragma unroll
        for (int j = 0; j < 8; j++) {
            float v = pairsum(acc1[i][j]) + sB1[tx + 16 * j];
            h[i][j] = v;
            s += v; s2 += v * v;
        }
        sRed[(r0 + i) * 16 + tx] = make_float2(s, s2);
    }
    __syncthreads();

    if (t < TILE_M) {
        float s = 0.f, s2 = 0.f;
        #pragma unroll
        for (int j = 0; j < 16; j++) { float2 v = sRed[t * 16 + j]; s += v.x; s2 += v.y; }
        float mu  = s * (1.0f / 128.0f);
        float var = s2 * (1.0f / 128.0f) - mu * mu;
        sStat[t] = make_float2(mu, rsqrtf(var + LN_EPS));
    }
    __syncthreads();

    // ---- LN + SiLU -> H (reuses sA region, stride HS) ----
    #pragma unroll
    for (int i = 0; i < 4; i++) {
        float2 st = sStat[r0 + i];
        #pragma unroll
        for (int j = 0; j < 8; j++) {
            int c = tx + 16 * j;
            float z = (h[i][j] - st.x) * st.y * sG[c] + sBt[c];
            float sg = 1.0f / (1.0f + __expf(-z));
            sH[(r0 + i) * HS + c] = z * sg;
        }
    }
    __syncthreads();

    // ---- GEMM2: k-parity f32x2, 4 rows x 4 cols per thread ----
    unsigned long long acc2[4][4];
    #pragma unroll
    for (int i = 0; i < 4; i++)
        #pragma unroll
        for (int j = 0; j < 4; j++) acc2[i][j] = 0ull;

    {
        const float* pH = sH + r0 * HS;
        const float* pW = sW2T + tx * W2TS;
        #pragma unroll 2
        for (int p = 0; p < PROJ_MID / 2; ++p) {
            unsigned long long a[4], w[4];
            #pragma unroll
            for (int i = 0; i < 4; i++) a[i] = lds64(pH + i * HS + 2 * p);
            #pragma unroll
            for (int j = 0; j < 4; j++) w[j] = lds64(pW + j * 16 * W2TS + 2 * p);
            #pragma unroll
            for (int i = 0; i < 4; i++)
                #pragma unroll
                for (int j = 0; j < 4; j++) ffma2(acc2[i][j], a[i], w[j]);
        }
    }

    #pragma unroll
    for (int i = 0; i < 4; i++) {
        size_t row = (size_t)(rowStart + r0 + i);
        #pragma unroll
        for (int j = 0; j < 4; j++) {
            int c = tx + 16 * j;
            out[row * OUT_DIM + c] = pairsum(acc2[i][j]) + sB2[c];
        }
    }
}

// ---------------------------------------------------------------------------
extern "C" void kernel_launch(void* const* d_in, const int* in_sizes, int n_in,
                              void* d_out, int out_size)
{
    const float* x    = (const float*)d_in[0];
    const int*   bidx = (const int*)d_in[1];
    const int*   pix  = (const int*)d_in[2];
    const int*   bkt  = (const int*)d_in[3];

    int iW1 = -1;
    for (int i = 4; i + 5 < n_in; ++i)
        if (in_sizes[i] == PROJ_IN * PROJ_MID && in_sizes[i + 1] == PROJ_MID) { iW1 = i; break; }
    if (iW1 < 0) {
        for (int i = 4; i < n_in; ++i)
            if (in_sizes[i] == PROJ_IN * PROJ_MID) { iW1 = i; break; }
    }
    const float* W1    = (const float*)d_in[iW1];
    const float* b1    = (const float*)d_in[iW1 + 1];
    const float* gamma = (const float*)d_in[iW1 + 2];
    const float* beta  = (const float*)d_in[iW1 + 3];
    const float* W2    = (const float*)d_in[iW1 + 4];
    const float* b2    = (const float*)d_in[iW1 + 5];
    float* out = (float*)d_out;

    int n = in_sizes[1];
    if (n <= 0) n = in_sizes[0] / C_IN;

    cudaFuncSetAttribute(k_mlp, cudaFuncAttributeMaxDynamicSharedMemorySize, SMEM_BYTES);

    int nblk = (n + 255) / 256;
    if (nblk > 65535) nblk = 65535;
    k_scatter<<<nblk, 256>>>((const float4*)x, bidx, pix, bkt, n);
    k_mlp<<<ROWS / TILE_M, MLP_THREADS, SMEM_BYTES>>>(W1, b1, gamma, beta, W2, b2, out);
}